// round 3
// baseline (speedup 1.0000x reference)
#include <cuda_runtime.h>
#include <cuda_bf16.h>
#include <math.h>
#include <stdint.h>

// Problem: B=8, S=1024, D=1024 -> N=8192 points, dim 1024.
#define NPTS 8192
#define DIM  1024
#define TI   128
#define TJ   128
#define BK   64            // k-chunk (bf16 elems): 128B rows -> 8x 16B units
#define NSTRIPS 8
#define JSTRIP (NPTS / NSTRIPS)
#define KSEL 5
#define P_THRESH 0.1f
#define TAU 32.0f

// Scratch in device globals (allocation-free rule)
__device__ float g_sq[NPTS];
__device__ float g_part[NPTS * NSTRIPS * KSEL];
__device__ float g_w[NPTS];
__device__ uint4 g_xbf4[NPTS * DIM / 8];   // bf16 copy of x_real, 8 bf16 per uint4

__device__ __forceinline__ uint32_t smaddr(const void* p) {
    return (uint32_t)__cvta_generic_to_shared(p);
}

// sorted ascending 5-array insertion
__device__ __forceinline__ void ins5(float (&tk)[KSEL], float v) {
    if (v < tk[4]) {
        tk[4] = v;
        if (tk[4] < tk[3]) { float t = tk[3]; tk[3] = tk[4]; tk[4] = t; }
        if (tk[3] < tk[2]) { float t = tk[2]; tk[2] = tk[3]; tk[3] = t; }
        if (tk[2] < tk[1]) { float t = tk[1]; tk[1] = tk[2]; tk[2] = t; }
        if (tk[1] < tk[0]) { float t = tk[0]; tk[0] = tk[1]; tk[1] = t; }
    }
}

// ---------------- K0: fp32 -> bf16 copy ----------------
__global__ void to_bf16_kernel(const float* __restrict__ xr) {
    const int row = blockIdx.x;
    const int t = threadIdx.x;                 // 128 threads x 8 elems
    const size_t base = (size_t)row * DIM + t * 8;
    const float4 f0 = *(const float4*)&xr[base];
    const float4 f1 = *(const float4*)&xr[base + 4];
    float fs[8] = {f0.x, f0.y, f0.z, f0.w, f1.x, f1.y, f1.z, f1.w};
    uint32_t ws[4];
    #pragma unroll
    for (int q = 0; q < 4; q++) {
        __nv_bfloat16 lo = __float2bfloat16_rn(fs[2 * q]);
        __nv_bfloat16 hi = __float2bfloat16_rn(fs[2 * q + 1]);
        ws[q] = ((uint32_t)(*(uint16_t*)&hi) << 16) | (uint32_t)(*(uint16_t*)&lo);
    }
    uint4 o; o.x = ws[0]; o.y = ws[1]; o.z = ws[2]; o.w = ws[3];
    g_xbf4[row * (DIM / 8) + t] = o;
}

// ---------------- K1: row squared norms (fp32, from original data) ----------------
__global__ void row_norms_kernel(const float* __restrict__ xr) {
    const int row = blockIdx.x;
    const int t = threadIdx.x;                 // 256 threads x float4
    const float4 v = *(const float4*)&xr[(size_t)row * DIM + t * 4];
    float s = v.x * v.x + v.y * v.y + v.z * v.z + v.w * v.w;
    #pragma unroll
    for (int o = 16; o > 0; o >>= 1) s += __shfl_down_sync(0xffffffffu, s, o);
    __shared__ float ws[8];
    if ((t & 31) == 0) ws[t >> 5] = s;
    __syncthreads();
    if (t == 0) {
        float tot = 0.f;
        #pragma unroll
        for (int w = 0; w < 8; w++) tot += ws[w];
        g_sq[row] = tot;
    }
}

// ---------------- K2: bf16 HMMA distance GEMM + online top-5 ----------------
// Block: 256 thr = 8 warps, 2(M) x 4(N) warp grid; warp tile 64x32; block tile 128x128.
__global__ __launch_bounds__(256, 1)
void dist_topk_kernel() {
    // union: [A tile 16KB | B tile 16KB] vs merge buffer 40KB
    __shared__ __align__(16) uint4 smraw[2560];          // 40960 bytes
    uint4* smA = smraw;                                  // 128 rows x 8 units
    uint4* smB = smraw + 1024;
    float* cand = (float*)smraw;                         // 128 x 16 x 5

    const int t = threadIdx.x;
    const int lane = t & 31;
    const int warp = t >> 5;
    const int warpM = warp >> 2;        // 0..1
    const int warpN = warp & 3;         // 0..3
    const int strip = blockIdx.x;       // 0..7
    const int iBase = blockIdx.y * TI;

    const uint32_t smA_base = smaddr(smA);
    const uint32_t smB_base = smaddr(smB);

    float tk[8][KSEL];
    #pragma unroll
    for (int r = 0; r < 8; r++)
        #pragma unroll
        for (int s = 0; s < KSEL; s++) tk[r][s] = 1e30f;

    float sqi[8];
    #pragma unroll
    for (int r8 = 0; r8 < 8; r8++) {
        const int mt = r8 >> 1, h = r8 & 1;
        sqi[r8] = g_sq[iBase + warpM * 64 + mt * 16 + h * 8 + (lane >> 2)];
    }

    // smem fill assignment: thread -> (row, 4 contiguous 16B units)
    const int ldRow = t >> 1;
    const int ldU0 = (t & 1) * 4;

    for (int jt = 0; jt < JSTRIP / TJ; jt++) {
        const int jBase = strip * JSTRIP + jt * TJ;

        float acc[4][4][4];
        #pragma unroll
        for (int mt = 0; mt < 4; mt++)
            #pragma unroll
            for (int nt = 0; nt < 4; nt++)
                #pragma unroll
                for (int c = 0; c < 4; c++) acc[mt][nt][c] = 0.0f;

        for (int kc = 0; kc < DIM; kc += BK) {
            __syncthreads();
            #pragma unroll
            for (int q = 0; q < 4; q++) {
                const int u = ldU0 + q;
                const int swz = u ^ (ldRow & 7);
                smA[(ldRow << 3) + swz] =
                    g_xbf4[(size_t)(iBase + ldRow) * (DIM / 8) + (kc >> 3) + u];
                smB[(ldRow << 3) + swz] =
                    g_xbf4[(size_t)(jBase + ldRow) * (DIM / 8) + (kc >> 3) + u];
            }
            __syncthreads();

            #pragma unroll
            for (int s = 0; s < 4; s++) {            // 4 k16-steps per chunk
                uint32_t af[4][4];
                #pragma unroll
                for (int mt = 0; mt < 4; mt++) {
                    const int grp = lane >> 3, rIn = lane & 7;
                    const int row = warpM * 64 + mt * 16 + ((grp & 1) << 3) + rIn;
                    const int ku = (s << 1) + (grp >> 1);
                    const uint32_t addr =
                        smA_base + (((row << 3) + (ku ^ (row & 7))) << 4);
                    asm volatile(
                        "ldmatrix.sync.aligned.m8n8.x4.shared.b16 {%0,%1,%2,%3}, [%4];"
                        : "=r"(af[mt][0]), "=r"(af[mt][1]),
                          "=r"(af[mt][2]), "=r"(af[mt][3])
                        : "r"(addr));
                }
                uint32_t bf[4][2];
                #pragma unroll
                for (int nt = 0; nt < 4; nt++) {
                    const int lg = lane & 15;
                    const int row = warpN * 32 + nt * 8 + (lg & 7);
                    const int ku = (s << 1) + (lg >> 3);
                    const uint32_t addr =
                        smB_base + (((row << 3) + (ku ^ (row & 7))) << 4);
                    asm volatile(
                        "ldmatrix.sync.aligned.m8n8.x2.shared.b16 {%0,%1}, [%2];"
                        : "=r"(bf[nt][0]), "=r"(bf[nt][1])
                        : "r"(addr));
                }
                #pragma unroll
                for (int mt = 0; mt < 4; mt++)
                    #pragma unroll
                    for (int nt = 0; nt < 4; nt++) {
                        asm volatile(
                            "mma.sync.aligned.m16n8k16.row.col.f32.bf16.bf16.f32 "
                            "{%0,%1,%2,%3}, {%4,%5,%6,%7}, {%8,%9}, {%0,%1,%2,%3};"
                            : "+f"(acc[mt][nt][0]), "+f"(acc[mt][nt][1]),
                              "+f"(acc[mt][nt][2]), "+f"(acc[mt][nt][3])
                            : "r"(af[mt][0]), "r"(af[mt][1]),
                              "r"(af[mt][2]), "r"(af[mt][3]),
                              "r"(bf[nt][0]), "r"(bf[nt][1]));
                    }
            }
        }

        // epilogue: dot -> distance -> top-5
        #pragma unroll
        for (int nt = 0; nt < 4; nt++) {
            const int jl0 = warpN * 32 + nt * 8 + ((lane & 3) << 1);
            const int j0 = jBase + jl0;
            const float sq0 = g_sq[j0];
            const float sq1 = g_sq[j0 + 1];
            #pragma unroll
            for (int mt = 0; mt < 4; mt++)
                #pragma unroll
                for (int h = 0; h < 2; h++) {
                    const int r8 = mt * 2 + h;
                    const int iRow = iBase + warpM * 64 + mt * 16 + h * 8 + (lane >> 2);
                    float d0 = sqi[r8] + sq0 - 2.0f * acc[mt][nt][h * 2 + 0];
                    float d1 = sqi[r8] + sq1 - 2.0f * acc[mt][nt][h * 2 + 1];
                    d0 = sqrtf(fmaxf(d0, 0.0f));
                    d1 = sqrtf(fmaxf(d1, 0.0f));
                    if (j0 == iRow)     d0 = 1e30f;   // exclude self
                    if (j0 + 1 == iRow) d1 = 1e30f;
                    ins5(tk[r8], d0);
                    ins5(tk[r8], d1);
                }
        }
    }

    // strip-end merge: 16 slots/row x 5 -> top-5 partial per row
    __syncthreads();
    #pragma unroll
    for (int r8 = 0; r8 < 8; r8++) {
        const int mt = r8 >> 1, h = r8 & 1;
        const int row = warpM * 64 + mt * 16 + h * 8 + (lane >> 2);
        const int slot = warpN * 4 + (lane & 3);
        #pragma unroll
        for (int s = 0; s < KSEL; s++)
            cand[row * (16 * KSEL) + slot * KSEL + s] = tk[r8][s];
    }
    __syncthreads();
    if (t < TI) {
        float best[KSEL] = {1e30f, 1e30f, 1e30f, 1e30f, 1e30f};
        #pragma unroll 4
        for (int q = 0; q < 16 * KSEL; q++)
            ins5(best, cand[t * (16 * KSEL) + q]);
        float* dst = &g_part[(size_t)(iBase + t) * (NSTRIPS * KSEL) + strip * KSEL];
        #pragma unroll
        for (int s = 0; s < KSEL; s++) dst[s] = best[s];
    }
}

// ---------------- K3: merge strips -> weight ----------------
__global__ void finalize_w_kernel() {
    const int i = blockIdx.x * blockDim.x + threadIdx.x;
    if (i >= NPTS) return;
    const float* p = &g_part[(size_t)i * NSTRIPS * KSEL];
    float best[KSEL] = {1e30f, 1e30f, 1e30f, 1e30f, 1e30f};
    #pragma unroll
    for (int q = 0; q < NSTRIPS * KSEL; q++) ins5(best, p[q]);
    const float score = (best[0] + best[1] + best[2] + best[3] + best[4]) * 0.2f;
    const float w = expf(-score / TAU);
    g_w[i] = (score > P_THRESH) ? w : 0.0f;
}

// ---------------- K4: apply weights ----------------
__global__ void apply_w_kernel(const float* __restrict__ xr,
                               const float* __restrict__ xi,
                               float* __restrict__ out) {
    const int row = blockIdx.x;
    const float w = g_w[row];
    const int t = threadIdx.x;                  // 256 threads x float4
    const size_t off = (size_t)row * DIM + t * 4;
    float4 a = *(const float4*)&xr[off];
    a.x *= w; a.y *= w; a.z *= w; a.w *= w;
    *(float4*)&out[off] = a;
    float4 b = *(const float4*)&xi[off];
    b.x *= w; b.y *= w; b.z *= w; b.w *= w;
    *(float4*)&out[(size_t)NPTS * DIM + off] = b;
}

extern "C" void kernel_launch(void* const* d_in, const int* in_sizes, int n_in,
                              void* d_out, int out_size) {
    const float* xr = (const float*)d_in[0];
    const float* xi = (const float*)d_in[1];
    float* out = (float*)d_out;

    to_bf16_kernel<<<NPTS, 128>>>(xr);
    row_norms_kernel<<<NPTS, 256>>>(xr);
    dist_topk_kernel<<<dim3(NSTRIPS, NPTS / TI), 256>>>();
    finalize_w_kernel<<<NPTS / 256, 256>>>();
    apply_w_kernel<<<NPTS, 256>>>(xr, xi, out);
}

// round 11
// speedup vs baseline: 1.3331x; 1.3331x over previous
#include <cuda_runtime.h>
#include <cuda_bf16.h>
#include <math.h>
#include <stdint.h>

// Problem: B=8, S=1024, D=1024 -> N=8192 points, dim 1024.
#define NPTS 8192
#define DIM  1024
#define TI   128
#define TJ   128
#define BK   64                          // k per chunk (bf16)
#define CPT  (DIM / BK)                  // 16 chunks per j-tile
#define NSTRIPS 8
#define JSTRIP (NPTS / NSTRIPS)          // 1024 j per CTA
#define NTILES (JSTRIP / TJ)             // 8 j-tiles per CTA
#define CHUNKS (NTILES * CPT)            // 128 chunks per CTA
#define KSEL 5
#define P_THRESH 0.1f
#define TAU 32.0f

__device__ float g_sq[NPTS];
__device__ float g_part[NPTS * NSTRIPS * KSEL];   // top-5 d^2 per strip
__device__ float g_w[NPTS];
__device__ uint4 g_xbf4[NPTS * DIM / 8];          // bf16 x_real, 8 per uint4

__device__ __forceinline__ uint32_t smaddr(const void* p) {
    return (uint32_t)__cvta_generic_to_shared(p);
}

// sorted ascending 5-array insertion
__device__ __forceinline__ void ins5(float (&tk)[KSEL], float v) {
    if (v < tk[4]) {
        tk[4] = v;
        if (tk[4] < tk[3]) { float t = tk[3]; tk[3] = tk[4]; tk[4] = t; }
        if (tk[3] < tk[2]) { float t = tk[2]; tk[2] = tk[3]; tk[3] = t; }
        if (tk[2] < tk[1]) { float t = tk[1]; tk[1] = tk[2]; tk[2] = t; }
        if (tk[1] < tk[0]) { float t = tk[0]; tk[0] = tk[1]; tk[1] = t; }
    }
}

// ---------------- K1: fused bf16 convert + row norms ----------------
__global__ void prep_kernel(const float* __restrict__ xr) {
    const int row = blockIdx.x;
    const int t = threadIdx.x;                  // 128 threads x 8 elems
    const size_t base = (size_t)row * DIM + t * 8;
    const float4 f0 = *(const float4*)&xr[base];
    const float4 f1 = *(const float4*)&xr[base + 4];
    float fs[8] = {f0.x, f0.y, f0.z, f0.w, f1.x, f1.y, f1.z, f1.w};
    float s = 0.f;
    uint32_t ws[4];
    #pragma unroll
    for (int q = 0; q < 4; q++) {
        s += fs[2*q] * fs[2*q] + fs[2*q+1] * fs[2*q+1];
        __nv_bfloat16 lo = __float2bfloat16_rn(fs[2*q]);
        __nv_bfloat16 hi = __float2bfloat16_rn(fs[2*q+1]);
        ws[q] = ((uint32_t)(*(uint16_t*)&hi) << 16) | (uint32_t)(*(uint16_t*)&lo);
    }
    uint4 o; o.x = ws[0]; o.y = ws[1]; o.z = ws[2]; o.w = ws[3];
    g_xbf4[row * (DIM / 8) + t] = o;
    #pragma unroll
    for (int off = 16; off > 0; off >>= 1) s += __shfl_down_sync(0xffffffffu, s, off);
    __shared__ float red[4];
    if ((t & 31) == 0) red[t >> 5] = s;
    __syncthreads();
    if (t == 0) g_sq[row] = red[0] + red[1] + red[2] + red[3];
}

// ---------------- K2: HMMA distance GEMM + online top-5 ----------------
// Same structure as the R3 kernel that PASSED (rel_err 2.4e-5), plus:
//  (a) register-prefetch double buffering (next chunk's LDGs issued before the
//      current chunk's MMAs -> latency hidden),
//  (b) top-5 on squared distances (sqrt deferred to finalize).
// 256 thr = 8 warps (2M x 4N), warp tile 64x32, block tile 128x128.
__global__ __launch_bounds__(256, 1)
void dist_topk_kernel() {
    __shared__ __align__(16) uint4 smraw[2560];   // 40KB: tiles (32KB) / merge (40KB)
    uint4* smA = smraw;                           // 128 rows x 8 units, swz u^(row&7)
    uint4* smB = smraw + 1024;
    float* cand = (float*)smraw;

    const int t = threadIdx.x;
    const int lane = t & 31;
    const int warp = t >> 5;
    const int warpM = warp >> 2;
    const int warpN = warp & 3;
    const int strip = blockIdx.x;
    const int iBase = blockIdx.y * TI;
    const uint32_t smA_base = smaddr(smA);
    const uint32_t smB_base = smaddr(smB);

    float tk[8][KSEL];
    #pragma unroll
    for (int r = 0; r < 8; r++)
        #pragma unroll
        for (int s = 0; s < KSEL; s++) tk[r][s] = 1e30f;

    float sqi[8];
    #pragma unroll
    for (int r8 = 0; r8 < 8; r8++) {
        const int mt = r8 >> 1, h = r8 & 1;
        sqi[r8] = g_sq[iBase + warpM * 64 + mt * 16 + h * 8 + (lane >> 2)];
    }

    // fill assignment (as R3): thread -> (row = t>>1, units ldU0..ldU0+3)
    const int ldRow = t >> 1;
    const int ldU0 = (t & 1) * 4;

    uint4 pa[4], pb[4];
    auto prefetch = [&](int c) {
        const int jt = c >> 4, kc = c & 15;
        const uint4* srcA = g_xbf4 + (size_t)(iBase + ldRow) * (DIM / 8) + kc * 8 + ldU0;
        const int jB = strip * JSTRIP + jt * TJ;
        const uint4* srcB = g_xbf4 + (size_t)(jB + ldRow) * (DIM / 8) + kc * 8 + ldU0;
        #pragma unroll
        for (int q = 0; q < 4; q++) { pa[q] = srcA[q]; pb[q] = srcB[q]; }
    };

    prefetch(0);

    float acc[4][4][4];
    #pragma unroll
    for (int mt = 0; mt < 4; mt++)
        #pragma unroll
        for (int nt = 0; nt < 4; nt++)
            #pragma unroll
            for (int q = 0; q < 4; q++) acc[mt][nt][q] = 0.0f;

    for (int c = 0; c < CHUNKS; c++) {
        // store prefetched chunk c into smem (layout identical to R3)
        #pragma unroll
        for (int q = 0; q < 4; q++) {
            const int u = ldU0 + q;
            const int swz = u ^ (ldRow & 7);
            smA[(ldRow << 3) + swz] = pa[q];
            smB[(ldRow << 3) + swz] = pb[q];
        }
        __syncthreads();

        if (c + 1 < CHUNKS) prefetch(c + 1);   // hide LDG latency behind MMAs

        #pragma unroll
        for (int s = 0; s < 4; s++) {          // 4 k16 steps per K64 chunk
            uint32_t af[4][4];
            #pragma unroll
            for (int mt = 0; mt < 4; mt++) {
                const int grp = lane >> 3, rIn = lane & 7;
                const int row = warpM * 64 + mt * 16 + ((grp & 1) << 3) + rIn;
                const int ku = (s << 1) + (grp >> 1);
                const uint32_t addr = smA_base + (((row << 3) + (ku ^ (row & 7))) << 4);
                asm volatile(
                    "ldmatrix.sync.aligned.m8n8.x4.shared.b16 {%0,%1,%2,%3}, [%4];"
                    : "=r"(af[mt][0]), "=r"(af[mt][1]),
                      "=r"(af[mt][2]), "=r"(af[mt][3])
                    : "r"(addr));
            }
            uint32_t bfr[4][2];
            #pragma unroll
            for (int nt = 0; nt < 4; nt++) {
                const int lg = lane & 15;
                const int row = warpN * 32 + nt * 8 + (lg & 7);
                const int ku = (s << 1) + (lg >> 3);
                const uint32_t addr = smB_base + (((row << 3) + (ku ^ (row & 7))) << 4);
                asm volatile(
                    "ldmatrix.sync.aligned.m8n8.x2.shared.b16 {%0,%1}, [%2];"
                    : "=r"(bfr[nt][0]), "=r"(bfr[nt][1])
                    : "r"(addr));
            }
            #pragma unroll
            for (int mt = 0; mt < 4; mt++)
                #pragma unroll
                for (int nt = 0; nt < 4; nt++)
                    asm volatile(
                        "mma.sync.aligned.m16n8k16.row.col.f32.bf16.bf16.f32 "
                        "{%0,%1,%2,%3}, {%4,%5,%6,%7}, {%8,%9}, {%0,%1,%2,%3};"
                        : "+f"(acc[mt][nt][0]), "+f"(acc[mt][nt][1]),
                          "+f"(acc[mt][nt][2]), "+f"(acc[mt][nt][3])
                        : "r"(af[mt][0]), "r"(af[mt][1]),
                          "r"(af[mt][2]), "r"(af[mt][3]),
                          "r"(bfr[nt][0]), "r"(bfr[nt][1]));
        }
        __syncthreads();

        if ((c & 15) == 15) {
            // end of j-tile: register-only epilogue, d^2 -> top-5
            const int jt = c >> 4;
            const int jBase = strip * JSTRIP + jt * TJ;
            #pragma unroll
            for (int nt = 0; nt < 4; nt++) {
                const int j0 = jBase + warpN * 32 + nt * 8 + ((lane & 3) << 1);
                const float sq0 = g_sq[j0];
                const float sq1 = g_sq[j0 + 1];
                #pragma unroll
                for (int mt = 0; mt < 4; mt++)
                    #pragma unroll
                    for (int h = 0; h < 2; h++) {
                        const int r8 = mt * 2 + h;
                        const int iRow = iBase + warpM * 64 + mt * 16 + h * 8 + (lane >> 2);
                        float d0 = fmaxf(fmaf(-2.0f, acc[mt][nt][h * 2 + 0], sqi[r8] + sq0), 0.0f);
                        float d1 = fmaxf(fmaf(-2.0f, acc[mt][nt][h * 2 + 1], sqi[r8] + sq1), 0.0f);
                        if (j0 == iRow)     d0 = 1e30f;   // exclude self
                        if (j0 + 1 == iRow) d1 = 1e30f;
                        ins5(tk[r8], d0);
                        ins5(tk[r8], d1);
                        acc[mt][nt][h * 2 + 0] = 0.0f;    // reset for next tile
                        acc[mt][nt][h * 2 + 1] = 0.0f;
                    }
            }
        }
    }

    // merge 16 candidate lists per row through smem (tiles done -> smem free)
    __syncthreads();
    #pragma unroll
    for (int r8 = 0; r8 < 8; r8++) {
        const int mt = r8 >> 1, h = r8 & 1;
        const int row = warpM * 64 + mt * 16 + h * 8 + (lane >> 2);
        const int slot = warpN * 4 + (lane & 3);
        #pragma unroll
        for (int s = 0; s < KSEL; s++)
            cand[row * (16 * KSEL) + slot * KSEL + s] = tk[r8][s];
    }
    __syncthreads();
    if (t < TI) {
        float best[KSEL] = {1e30f, 1e30f, 1e30f, 1e30f, 1e30f};
        #pragma unroll 4
        for (int q = 0; q < 16 * KSEL; q++)
            ins5(best, cand[t * (16 * KSEL) + q]);
        float* dst = &g_part[(size_t)(iBase + t) * (NSTRIPS * KSEL) + strip * KSEL];
        #pragma unroll
        for (int s = 0; s < KSEL; s++) dst[s] = best[s];
    }
}

// ---------------- K3: merge strips -> weight ----------------
__global__ void finalize_w_kernel() {
    const int i = blockIdx.x * blockDim.x + threadIdx.x;
    if (i >= NPTS) return;
    const float* p = &g_part[(size_t)i * NSTRIPS * KSEL];
    float best[KSEL] = {1e30f, 1e30f, 1e30f, 1e30f, 1e30f};
    #pragma unroll
    for (int q = 0; q < NSTRIPS * KSEL; q++) ins5(best, p[q]);
    const float score = (sqrtf(best[0]) + sqrtf(best[1]) + sqrtf(best[2]) +
                         sqrtf(best[3]) + sqrtf(best[4])) * 0.2f;
    const float w = expf(-score / TAU);
    g_w[i] = (score > P_THRESH) ? w : 0.0f;
}

// ---------------- K4: apply weights ----------------
__global__ void apply_w_kernel(const float* __restrict__ xr,
                               const float* __restrict__ xi,
                               float* __restrict__ out) {
    const int row = blockIdx.x;
    const float w = g_w[row];
    const int t = threadIdx.x;
    const size_t off = (size_t)row * DIM + t * 4;
    float4 a = *(const float4*)&xr[off];
    a.x *= w; a.y *= w; a.z *= w; a.w *= w;
    *(float4*)&out[off] = a;
    float4 b = *(const float4*)&xi[off];
    b.x *= w; b.y *= w; b.z *= w; b.w *= w;
    *(float4*)&out[(size_t)NPTS * DIM + off] = b;
}

extern "C" void kernel_launch(void* const* d_in, const int* in_sizes, int n_in,
                              void* d_out, int out_size) {
    const float* xr = (const float*)d_in[0];
    const float* xi = (const float*)d_in[1];
    float* out = (float*)d_out;

    prep_kernel<<<NPTS, 128>>>(xr);
    dist_topk_kernel<<<dim3(NSTRIPS, NPTS / TI), 256>>>();
    finalize_w_kernel<<<NPTS / 256, 256>>>();
    apply_w_kernel<<<NPTS, 256>>>(xr, xi, out);
}

// round 13
// speedup vs baseline: 1.5674x; 1.1758x over previous
#include <cuda_runtime.h>
#include <cuda_bf16.h>
#include <math.h>
#include <stdint.h>

// Problem: B=8, S=1024, D=1024 -> N=8192 points, dim 1024.
// R12 resubmission (R12 never executed: broker-level container flake).
#define NPTS 8192
#define DIM  1024
#define TI   128
#define TJ   128
#define BK   64                          // k per chunk (bf16)
#define CPT  (DIM / BK)                  // 16 chunks per j-tile
#define NSTRIPS 8
#define JSTRIP (NPTS / NSTRIPS)          // 1024 j per CTA
#define NTILES (JSTRIP / TJ)             // 8 j-tiles per CTA
#define CHUNKS (NTILES * CPT)            // 128 chunks per CTA
#define KSEL 5
#define P_THRESH 0.1f
#define TAU 32.0f

__device__ float g_sq[NPTS];
__device__ float g_part[NPTS * NSTRIPS * KSEL];   // top-5 d^2 per strip
__device__ float g_w[NPTS];
__device__ uint4 g_xbf4[NPTS * DIM / 8];          // bf16 x_real, 8 per uint4

__device__ __forceinline__ uint32_t smaddr(const void* p) {
    return (uint32_t)__cvta_generic_to_shared(p);
}

// sorted ascending 5-array insertion
__device__ __forceinline__ void ins5(float (&tk)[KSEL], float v) {
    if (v < tk[4]) {
        tk[4] = v;
        if (tk[4] < tk[3]) { float t = tk[3]; tk[3] = tk[4]; tk[4] = t; }
        if (tk[3] < tk[2]) { float t = tk[2]; tk[2] = tk[3]; tk[3] = t; }
        if (tk[2] < tk[1]) { float t = tk[1]; tk[1] = tk[2]; tk[2] = t; }
        if (tk[1] < tk[0]) { float t = tk[0]; tk[0] = tk[1]; tk[1] = t; }
    }
}

// ---------------- K1: fused bf16 convert + row norms ----------------
__global__ void prep_kernel(const float* __restrict__ xr) {
    const int row = blockIdx.x;
    const int t = threadIdx.x;                  // 128 threads x 8 elems
    const size_t base = (size_t)row * DIM + t * 8;
    const float4 f0 = *(const float4*)&xr[base];
    const float4 f1 = *(const float4*)&xr[base + 4];
    float fs[8] = {f0.x, f0.y, f0.z, f0.w, f1.x, f1.y, f1.z, f1.w};
    float s = 0.f;
    uint32_t ws[4];
    #pragma unroll
    for (int q = 0; q < 4; q++) {
        s += fs[2*q] * fs[2*q] + fs[2*q+1] * fs[2*q+1];
        __nv_bfloat16 lo = __float2bfloat16_rn(fs[2*q]);
        __nv_bfloat16 hi = __float2bfloat16_rn(fs[2*q+1]);
        ws[q] = ((uint32_t)(*(uint16_t*)&hi) << 16) | (uint32_t)(*(uint16_t*)&lo);
    }
    uint4 o; o.x = ws[0]; o.y = ws[1]; o.z = ws[2]; o.w = ws[3];
    g_xbf4[row * (DIM / 8) + t] = o;
    #pragma unroll
    for (int off = 16; off > 0; off >>= 1) s += __shfl_down_sync(0xffffffffu, s, off);
    __shared__ float red[4];
    if ((t & 31) == 0) red[t >> 5] = s;
    __syncthreads();
    if (t == 0) g_sq[row] = red[0] + red[1] + red[2] + red[3];
}

// ---------------- K2: HMMA distance GEMM + online top-5 ----------------
// 512 thr = 16 warps (4M x 4N), warp tile 32x32, block tile 128x128.
// Register-prefetch double buffering; top-5 on squared distances.
// ~115 regs/thread -> 16 warps/SM (4 per SMSP) for latency hiding.
__global__ __launch_bounds__(512, 1)
void dist_topk_kernel() {
    __shared__ __align__(16) uint4 smraw[2560];   // 40KB: tiles (32KB) / merge (40KB)
    uint4* smA = smraw;                           // 128 rows x 8 units, swz u^(row&7)
    uint4* smB = smraw + 1024;
    float* cand = (float*)smraw;

    const int t = threadIdx.x;
    const int lane = t & 31;
    const int warp = t >> 5;                      // 0..15
    const int warpM = warp >> 2;                  // 0..3 (32-row strips)
    const int warpN = warp & 3;                   // 0..3 (32-col strips)
    const int strip = blockIdx.x;
    const int iBase = blockIdx.y * TI;
    const uint32_t smA_base = smaddr(smA);
    const uint32_t smB_base = smaddr(smB);

    float tk[4][KSEL];
    #pragma unroll
    for (int r = 0; r < 4; r++)
        #pragma unroll
        for (int s = 0; s < KSEL; s++) tk[r][s] = 1e30f;

    float sqi[4];
    #pragma unroll
    for (int r4 = 0; r4 < 4; r4++) {
        const int mt = r4 >> 1, h = r4 & 1;
        sqi[r4] = g_sq[iBase + warpM * 32 + mt * 16 + h * 8 + (lane >> 2)];
    }

    // fill assignment: 512 threads -> row = t>>2 (0..127), units ldU0, ldU0+1
    const int ldRow = t >> 2;
    const int ldU0 = (t & 3) * 2;

    uint4 pa[2], pb[2];
    auto prefetch = [&](int c) {
        const int jt = c >> 4, kc = c & 15;
        const uint4* srcA = g_xbf4 + (size_t)(iBase + ldRow) * (DIM / 8) + kc * 8 + ldU0;
        const int jB = strip * JSTRIP + jt * TJ;
        const uint4* srcB = g_xbf4 + (size_t)(jB + ldRow) * (DIM / 8) + kc * 8 + ldU0;
        #pragma unroll
        for (int q = 0; q < 2; q++) { pa[q] = srcA[q]; pb[q] = srcB[q]; }
    };

    prefetch(0);

    float acc[2][4][4];
    #pragma unroll
    for (int mt = 0; mt < 2; mt++)
        #pragma unroll
        for (int nt = 0; nt < 4; nt++)
            #pragma unroll
            for (int q = 0; q < 4; q++) acc[mt][nt][q] = 0.0f;

    for (int c = 0; c < CHUNKS; c++) {
        // store prefetched chunk c into smem (swizzle identical to validated R3)
        #pragma unroll
        for (int q = 0; q < 2; q++) {
            const int u = ldU0 + q;
            const int swz = u ^ (ldRow & 7);
            smA[(ldRow << 3) + swz] = pa[q];
            smB[(ldRow << 3) + swz] = pb[q];
        }
        __syncthreads();

        if (c + 1 < CHUNKS) prefetch(c + 1);   // hide LDG latency behind MMAs

        #pragma unroll
        for (int s = 0; s < 4; s++) {          // 4 k16 steps per K64 chunk
            uint32_t af[2][4];
            #pragma unroll
            for (int mt = 0; mt < 2; mt++) {
                const int grp = lane >> 3, rIn = lane & 7;
                const int row = warpM * 32 + mt * 16 + ((grp & 1) << 3) + rIn;
                const int ku = (s << 1) + (grp >> 1);
                const uint32_t addr = smA_base + (((row << 3) + (ku ^ (row & 7))) << 4);
                asm volatile(
                    "ldmatrix.sync.aligned.m8n8.x4.shared.b16 {%0,%1,%2,%3}, [%4];"
                    : "=r"(af[mt][0]), "=r"(af[mt][1]),
                      "=r"(af[mt][2]), "=r"(af[mt][3])
                    : "r"(addr));
            }
            uint32_t bfr[4][2];
            #pragma unroll
            for (int nt = 0; nt < 4; nt++) {
                const int lg = lane & 15;
                const int row = warpN * 32 + nt * 8 + (lg & 7);
                const int ku = (s << 1) + (lg >> 3);
                const uint32_t addr = smB_base + (((row << 3) + (ku ^ (row & 7))) << 4);
                asm volatile(
                    "ldmatrix.sync.aligned.m8n8.x2.shared.b16 {%0,%1}, [%2];"
                    : "=r"(bfr[nt][0]), "=r"(bfr[nt][1])
                    : "r"(addr));
            }
            #pragma unroll
            for (int mt = 0; mt < 2; mt++)
                #pragma unroll
                for (int nt = 0; nt < 4; nt++)
                    asm volatile(
                        "mma.sync.aligned.m16n8k16.row.col.f32.bf16.bf16.f32 "
                        "{%0,%1,%2,%3}, {%4,%5,%6,%7}, {%8,%9}, {%0,%1,%2,%3};"
                        : "+f"(acc[mt][nt][0]), "+f"(acc[mt][nt][1]),
                          "+f"(acc[mt][nt][2]), "+f"(acc[mt][nt][3])
                        : "r"(af[mt][0]), "r"(af[mt][1]),
                          "r"(af[mt][2]), "r"(af[mt][3]),
                          "r"(bfr[nt][0]), "r"(bfr[nt][1]));
        }
        __syncthreads();

        if ((c & 15) == 15) {
            // end of j-tile: register-only epilogue, d^2 -> top-5
            const int jt = c >> 4;
            const int jBase = strip * JSTRIP + jt * TJ;
            #pragma unroll
            for (int nt = 0; nt < 4; nt++) {
                const int j0 = jBase + warpN * 32 + nt * 8 + ((lane & 3) << 1);
                const float sq0 = g_sq[j0];
                const float sq1 = g_sq[j0 + 1];
                #pragma unroll
                for (int mt = 0; mt < 2; mt++)
                    #pragma unroll
                    for (int h = 0; h < 2; h++) {
                        const int r4 = mt * 2 + h;
                        const int iRow = iBase + warpM * 32 + mt * 16 + h * 8 + (lane >> 2);
                        float d0 = fmaxf(fmaf(-2.0f, acc[mt][nt][h * 2 + 0], sqi[r4] + sq0), 0.0f);
                        float d1 = fmaxf(fmaf(-2.0f, acc[mt][nt][h * 2 + 1], sqi[r4] + sq1), 0.0f);
                        if (j0 == iRow)     d0 = 1e30f;   // exclude self
                        if (j0 + 1 == iRow) d1 = 1e30f;
                        ins5(tk[r4], d0);
                        ins5(tk[r4], d1);
                        acc[mt][nt][h * 2 + 0] = 0.0f;    // reset for next tile
                        acc[mt][nt][h * 2 + 1] = 0.0f;
                    }
            }
        }
    }

    // merge 16 candidate lists per row through smem (tiles done -> smem free)
    __syncthreads();
    #pragma unroll
    for (int r4 = 0; r4 < 4; r4++) {
        const int mt = r4 >> 1, h = r4 & 1;
        const int row = warpM * 32 + mt * 16 + h * 8 + (lane >> 2);
        const int slot = warpN * 4 + (lane & 3);
        #pragma unroll
        for (int s = 0; s < KSEL; s++)
            cand[row * (16 * KSEL) + slot * KSEL + s] = tk[r4][s];
    }
    __syncthreads();
    if (t < TI) {
        float best[KSEL] = {1e30f, 1e30f, 1e30f, 1e30f, 1e30f};
        #pragma unroll 4
        for (int q = 0; q < 16 * KSEL; q++)
            ins5(best, cand[t * (16 * KSEL) + q]);
        float* dst = &g_part[(size_t)(iBase + t) * (NSTRIPS * KSEL) + strip * KSEL];
        #pragma unroll
        for (int s = 0; s < KSEL; s++) dst[s] = best[s];
    }
}

// ---------------- K3: merge strips -> weight ----------------
__global__ void finalize_w_kernel() {
    const int i = blockIdx.x * blockDim.x + threadIdx.x;
    if (i >= NPTS) return;
    const float* p = &g_part[(size_t)i * NSTRIPS * KSEL];
    float best[KSEL] = {1e30f, 1e30f, 1e30f, 1e30f, 1e30f};
    #pragma unroll
    for (int q = 0; q < NSTRIPS * KSEL; q++) ins5(best, p[q]);
    const float score = (sqrtf(best[0]) + sqrtf(best[1]) + sqrtf(best[2]) +
                         sqrtf(best[3]) + sqrtf(best[4])) * 0.2f;
    const float w = expf(-score / TAU);
    g_w[i] = (score > P_THRESH) ? w : 0.0f;
}

// ---------------- K4: apply weights ----------------
__global__ void apply_w_kernel(const float* __restrict__ xr,
                               const float* __restrict__ xi,
                               float* __restrict__ out) {
    const int row = blockIdx.x;
    const float w = g_w[row];
    const int t = threadIdx.x;
    const size_t off = (size_t)row * DIM + t * 4;
    float4 a = *(const float4*)&xr[off];
    a.x *= w; a.y *= w; a.z *= w; a.w *= w;
    *(float4*)&out[off] = a;
    float4 b = *(const float4*)&xi[off];
    b.x *= w; b.y *= w; b.z *= w; b.w *= w;
    *(float4*)&out[(size_t)NPTS * DIM + off] = b;
}

extern "C" void kernel_launch(void* const* d_in, const int* in_sizes, int n_in,
                              void* d_out, int out_size) {
    const float* xr = (const float*)d_in[0];
    const float* xi = (const float*)d_in[1];
    float* out = (float*)d_out;

    prep_kernel<<<NPTS, 128>>>(xr);
    dist_topk_kernel<<<dim3(NSTRIPS, NPTS / TI), 512>>>();
    finalize_w_kernel<<<NPTS / 256, 256>>>();
    apply_w_kernel<<<NPTS, 256>>>(xr, xi, out);
}